// round 1
// baseline (speedup 1.0000x reference)
#include <cuda_runtime.h>
#include <cuda_bf16.h>
#include <stdint.h>

#define Bb 256
#define Tt 512
#define Ee 512
#define Hh 1024
#define G4 4096
#define KT 1536   // E + H
#define Mm 1024
#define VOC 32001

// ---------------- static device scratch (no allocations allowed) ----------------
__device__ __nv_bfloat16 g_emb16[(size_t)VOC * Ee];      // 32.8 MB
__device__ __nv_bfloat16 g_Wcat[(size_t)G4 * KT];        // 12.6 MB  rows: gate*1024+j, cols: [W_ih | W_hh]
__device__ float         g_bias[G4];                     // b_ih + b_hh
__device__ float         g_c[Bb * Hh];
__device__ __nv_bfloat16 g_h[2][Bb * Hh];                // double buffered (cross-block race otherwise)
__device__ float         g_hn[Bb * Hh];
__device__ float         g_z[Bb * Mm];

// ---------------- setup kernels ----------------
__global__ void k_setup_emb(const float* __restrict__ emb) {
    int i4 = blockIdx.x * blockDim.x + threadIdx.x;
    const int n4 = (VOC * Ee) / 4;
    if (i4 >= n4) return;
    float4 v = reinterpret_cast<const float4*>(emb)[i4];
    __nv_bfloat162 p0 = __floats2bfloat162_rn(v.x, v.y);
    __nv_bfloat162 p1 = __floats2bfloat162_rn(v.z, v.w);
    reinterpret_cast<__nv_bfloat162*>(g_emb16)[i4 * 2 + 0] = p0;
    reinterpret_cast<__nv_bfloat162*>(g_emb16)[i4 * 2 + 1] = p1;
}

__global__ void k_setup_w(const float* __restrict__ Wih, const float* __restrict__ Whh) {
    int i4 = blockIdx.x * blockDim.x + threadIdx.x;
    const int n4 = (G4 * KT) / 4;
    if (i4 >= n4) return;
    int idx = i4 * 4;
    int j = idx / KT;
    int k = idx % KT;
    float4 v;
    if (k < Ee) v = *reinterpret_cast<const float4*>(&Wih[(size_t)j * Ee + k]);
    else        v = *reinterpret_cast<const float4*>(&Whh[(size_t)j * Hh + (k - Ee)]);
    __nv_bfloat162 p0 = __floats2bfloat162_rn(v.x, v.y);
    __nv_bfloat162 p1 = __floats2bfloat162_rn(v.z, v.w);
    reinterpret_cast<__nv_bfloat162*>(g_Wcat)[i4 * 2 + 0] = p0;
    reinterpret_cast<__nv_bfloat162*>(g_Wcat)[i4 * 2 + 1] = p1;
}

__global__ void k_setup_state(const float* __restrict__ h0, const float* __restrict__ c0,
                              const float* __restrict__ b_ih, const float* __restrict__ b_hh) {
    int i = blockIdx.x * blockDim.x + threadIdx.x;
    if (i < Bb * Hh) {
        g_c[i] = c0[i];
        g_h[0][i] = __float2bfloat16(h0[i]);
    }
    if (i < G4) g_bias[i] = b_ih[i] + b_hh[i];
}

// ---------------- bf16 mma helper: m16n8k16 row.col f32 accum ----------------
__device__ __forceinline__ void mma16816(float* d, const uint32_t* a, const uint32_t* b) {
    asm volatile(
        "mma.sync.aligned.m16n8k16.row.col.f32.bf16.bf16.f32 "
        "{%0,%1,%2,%3}, {%4,%5,%6,%7}, {%8,%9}, {%0,%1,%2,%3};\n"
        : "+f"(d[0]), "+f"(d[1]), "+f"(d[2]), "+f"(d[3])
        : "r"(a[0]), "r"(a[1]), "r"(a[2]), "r"(a[3]), "r"(b[0]), "r"(b[1]));
}

// ---------------- fused LSTM step ----------------
// grid (32, 4): blockIdx.x -> 32 h-columns (n0), blockIdx.y -> 64 batches (b0)
// Each block computes gates[b0:b0+64, {g*1024+n0 .. +31, g=0..3}] = A @ Wcat^T
// where A = [ emb[x[b,t]] | h_{t-1}[b] ]  (K = 1536, bf16), then performs the
// LSTM pointwise update in the epilogue (fp32 state).
__global__ __launch_bounds__(256) void k_lstm_step(const int* __restrict__ x,
                                                   const int* __restrict__ x_index,
                                                   int t) {
    __shared__ __align__(16) char smraw[64 * 132 * 4];   // 33792 B, unioned usage
    __shared__ int s_tok[64];

    __nv_bfloat16 (*sA)[40] = reinterpret_cast<__nv_bfloat16(*)[40]>(smraw);              // [64][40]
    __nv_bfloat16 (*sB)[40] = reinterpret_cast<__nv_bfloat16(*)[40]>(smraw + 64 * 40 * 2); // [128][40]
    float (*sAcc)[132] = reinterpret_cast<float(*)[132]>(smraw);                            // [64][132]

    const int tid = threadIdx.x;
    const int b0 = blockIdx.y * 64;
    const int n0 = blockIdx.x * 32;

    const __nv_bfloat16* __restrict__ hread = g_h[t & 1];
    __nv_bfloat16* __restrict__ hwrite = g_h[(t + 1) & 1];

    if (tid < 64) s_tok[tid] = x[(b0 + tid) * Tt + t];
    __syncthreads();

    // global->smem load assignments
    const int lrow = tid >> 2;          // 0..63
    const int lk = (tid & 3) * 8;       // 0,8,16,24 (bf16 elems)
    const int tok = s_tok[lrow];
    const __nv_bfloat16* __restrict__ embp = g_emb16 + (size_t)tok * Ee;
    const __nv_bfloat16* __restrict__ hp = hread + (size_t)(b0 + lrow) * Hh;
    const int r1 = lrow + 64;
    const int wr0 = (lrow >> 5) * Hh + n0 + (lrow & 31);  // gates 0,1
    const int wr1 = (r1 >> 5) * Hh + n0 + (r1 & 31);      // gates 2,3
    const __nv_bfloat16* __restrict__ wp0 = g_Wcat + (size_t)wr0 * KT;
    const __nv_bfloat16* __restrict__ wp1 = g_Wcat + (size_t)wr1 * KT;

    const int warp = tid >> 5;
    const int lane = tid & 31;
    const int wm = warp >> 2;            // 0..1 -> m base
    const int wn = warp & 3;             // 0..3 -> n base
    const int mbase = wm * 32;
    const int nbase = wn * 32;
    const int fr = lane >> 2;            // fragment row group
    const int fc = (lane & 3) * 2;       // fragment col pair

    float acc[2][4][4];
#pragma unroll
    for (int mt = 0; mt < 2; ++mt)
#pragma unroll
        for (int nt = 0; nt < 4; ++nt)
#pragma unroll
            for (int e = 0; e < 4; ++e) acc[mt][nt][e] = 0.0f;

    // prefetch tile 0
    uint4 a_pf = (0 < Ee) ? *reinterpret_cast<const uint4*>(embp + 0 + lk)
                          : *reinterpret_cast<const uint4*>(hp + 0 + lk);
    uint4 b0_pf = *reinterpret_cast<const uint4*>(wp0 + 0 + lk);
    uint4 b1_pf = *reinterpret_cast<const uint4*>(wp1 + 0 + lk);

    const int NIT = KT / 32;  // 48
    for (int it = 0; it < NIT; ++it) {
        *reinterpret_cast<uint4*>(&sA[lrow][lk]) = a_pf;
        *reinterpret_cast<uint4*>(&sB[lrow][lk]) = b0_pf;
        *reinterpret_cast<uint4*>(&sB[r1][lk]) = b1_pf;
        __syncthreads();

        if (it + 1 < NIT) {
            int k0 = (it + 1) * 32;
            a_pf = (k0 < Ee) ? *reinterpret_cast<const uint4*>(embp + k0 + lk)
                             : *reinterpret_cast<const uint4*>(hp + (k0 - Ee) + lk);
            b0_pf = *reinterpret_cast<const uint4*>(wp0 + k0 + lk);
            b1_pf = *reinterpret_cast<const uint4*>(wp1 + k0 + lk);
        }

#pragma unroll
        for (int ks = 0; ks < 32; ks += 16) {
            uint32_t afrag[2][4], bfrag[4][2];
#pragma unroll
            for (int mt = 0; mt < 2; ++mt) {
                int m0 = mbase + mt * 16;
                afrag[mt][0] = *reinterpret_cast<const uint32_t*>(&sA[m0 + fr][ks + fc]);
                afrag[mt][1] = *reinterpret_cast<const uint32_t*>(&sA[m0 + 8 + fr][ks + fc]);
                afrag[mt][2] = *reinterpret_cast<const uint32_t*>(&sA[m0 + fr][ks + 8 + fc]);
                afrag[mt][3] = *reinterpret_cast<const uint32_t*>(&sA[m0 + 8 + fr][ks + 8 + fc]);
            }
#pragma unroll
            for (int nt = 0; nt < 4; ++nt) {
                int nn = nbase + nt * 8 + fr;
                bfrag[nt][0] = *reinterpret_cast<const uint32_t*>(&sB[nn][ks + fc]);
                bfrag[nt][1] = *reinterpret_cast<const uint32_t*>(&sB[nn][ks + 8 + fc]);
            }
#pragma unroll
            for (int mt = 0; mt < 2; ++mt)
#pragma unroll
                for (int nt = 0; nt < 4; ++nt)
                    mma16816(acc[mt][nt], afrag[mt], bfrag[nt]);
        }
        __syncthreads();
    }

    // epilogue: stage accumulators to smem (cols: gate*32 + jj)
#pragma unroll
    for (int mt = 0; mt < 2; ++mt)
#pragma unroll
        for (int nt = 0; nt < 4; ++nt) {
            int m = mbase + mt * 16 + fr;
            int n = nbase + nt * 8 + fc;
            sAcc[m][n]     = acc[mt][nt][0];
            sAcc[m][n + 1] = acc[mt][nt][1];
            sAcc[m + 8][n]     = acc[mt][nt][2];
            sAcc[m + 8][n + 1] = acc[mt][nt][3];
        }
    __syncthreads();

    // LSTM pointwise update: 64 batches x 32 h-cols = 2048 items
#pragma unroll
    for (int w = 0; w < 8; ++w) {
        int idx = w * 256 + tid;
        int bb = idx >> 5;
        int jj = idx & 31;
        int j = n0 + jj;
        float ig = sAcc[bb][jj]      + g_bias[j];
        float fg = sAcc[bb][32 + jj] + g_bias[Hh + j];
        float gg = sAcc[bb][64 + jj] + g_bias[2 * Hh + j];
        float og = sAcc[bb][96 + jj] + g_bias[3 * Hh + j];
        float iv = 1.0f / (1.0f + expf(-ig));
        float fv = 1.0f / (1.0f + expf(-fg));
        float gv = tanhf(gg);
        float ov = 1.0f / (1.0f + expf(-og));
        int gi = (b0 + bb) * Hh + j;
        float cv = fv * g_c[gi] + iv * gv;
        g_c[gi] = cv;
        float hv = ov * tanhf(cv);
        hwrite[gi] = __float2bfloat16(hv);
        if (x_index[b0 + bb] == t) g_hn[gi] = hv;
    }
}

// ---------------- fc1: z = tanh(hn @ fc1_w^T + fc1_b), fp32 ----------------
// grid (16, 4), 256 threads, 64x64 tiles, 4x4 micro-tiles
__global__ __launch_bounds__(256) void k_fc1(const float* __restrict__ fc1_w,
                                             const float* __restrict__ fc1_b) {
    __shared__ float sA[16][68];  // [k][b]
    __shared__ float sB[16][68];  // [k][n]
    const int tid = threadIdx.x;
    const int b0 = blockIdx.y * 64;
    const int n0 = blockIdx.x * 64;
    const int tx = tid & 15, ty = tid >> 4;
    const int lr = tid & 63;
    const int lc4 = (tid >> 6) * 4;

    float acc[4][4];
#pragma unroll
    for (int i = 0; i < 4; ++i)
#pragma unroll
        for (int jn = 0; jn < 4; ++jn) acc[i][jn] = 0.0f;

    for (int k0 = 0; k0 < Hh; k0 += 16) {
        float4 va = *reinterpret_cast<const float4*>(&g_hn[(size_t)(b0 + lr) * Hh + k0 + lc4]);
        float4 vb = *reinterpret_cast<const float4*>(&fc1_w[(size_t)(n0 + lr) * Hh + k0 + lc4]);
        __syncthreads();
        sA[lc4 + 0][lr] = va.x; sA[lc4 + 1][lr] = va.y; sA[lc4 + 2][lr] = va.z; sA[lc4 + 3][lr] = va.w;
        sB[lc4 + 0][lr] = vb.x; sB[lc4 + 1][lr] = vb.y; sB[lc4 + 2][lr] = vb.z; sB[lc4 + 3][lr] = vb.w;
        __syncthreads();
#pragma unroll
        for (int k = 0; k < 16; ++k) {
            float4 ra4 = *reinterpret_cast<const float4*>(&sA[k][ty * 4]);
            float4 rb4 = *reinterpret_cast<const float4*>(&sB[k][tx * 4]);
            float ra[4] = {ra4.x, ra4.y, ra4.z, ra4.w};
            float rb[4] = {rb4.x, rb4.y, rb4.z, rb4.w};
#pragma unroll
            for (int i = 0; i < 4; ++i)
#pragma unroll
                for (int jn = 0; jn < 4; ++jn) acc[i][jn] += ra[i] * rb[jn];
        }
    }
#pragma unroll
    for (int i = 0; i < 4; ++i)
#pragma unroll
        for (int jn = 0; jn < 4; ++jn) {
            int bb = b0 + ty * 4 + i;
            int nn = n0 + tx * 4 + jn;
            g_z[(size_t)bb * Mm + nn] = tanhf(acc[i][jn] + fc1_b[nn]);
        }
}

// ---------------- fc2 + log_softmax (O=2) ----------------
__global__ __launch_bounds__(128) void k_fc2(const float* __restrict__ fc2_w,
                                             const float* __restrict__ fc2_b,
                                             float* __restrict__ out) {
    const int b = blockIdx.x;
    const int tid = threadIdx.x;
    float p0 = 0.f, p1 = 0.f;
    for (int k = tid; k < Mm; k += 128) {
        float zv = g_z[(size_t)b * Mm + k];
        p0 += zv * fc2_w[k];
        p1 += zv * fc2_w[Mm + k];
    }
#pragma unroll
    for (int off = 16; off; off >>= 1) {
        p0 += __shfl_down_sync(0xffffffffu, p0, off);
        p1 += __shfl_down_sync(0xffffffffu, p1, off);
    }
    __shared__ float s0[4], s1[4];
    if ((tid & 31) == 0) { s0[tid >> 5] = p0; s1[tid >> 5] = p1; }
    __syncthreads();
    if (tid == 0) {
        float l0 = s0[0] + s0[1] + s0[2] + s0[3] + fc2_b[0];
        float l1 = s1[0] + s1[1] + s1[2] + s1[3] + fc2_b[1];
        float mx = fmaxf(l0, l1);
        float lse = mx + logf(expf(l0 - mx) + expf(l1 - mx));
        out[b * 2 + 0] = l0 - lse;
        out[b * 2 + 1] = l1 - lse;
    }
}

// ---------------- launch ----------------
extern "C" void kernel_launch(void* const* d_in, const int* in_sizes, int n_in,
                              void* d_out, int out_size) {
    const int*   x       = (const int*)d_in[0];
    const int*   x_index = (const int*)d_in[1];
    const float* emb     = (const float*)d_in[2];
    const float* W_ih    = (const float*)d_in[3];
    const float* W_hh    = (const float*)d_in[4];
    const float* b_ih    = (const float*)d_in[5];
    const float* b_hh    = (const float*)d_in[6];
    const float* fc1_w   = (const float*)d_in[7];
    const float* fc1_b   = (const float*)d_in[8];
    const float* fc2_w   = (const float*)d_in[9];
    const float* fc2_b   = (const float*)d_in[10];
    const float* h0      = (const float*)d_in[11];
    const float* c0      = (const float*)d_in[12];
    float* out = (float*)d_out;

    (void)in_sizes; (void)n_in; (void)out_size;

    k_setup_emb<<<(VOC * Ee / 4 + 255) / 256, 256>>>(emb);
    k_setup_w<<<(G4 * KT / 4 + 255) / 256, 256>>>(W_ih, W_hh);
    k_setup_state<<<(Bb * Hh + 255) / 256, 256>>>(h0, c0, b_ih, b_hh);

    dim3 sgrid(Hh / 32, Bb / 64);  // (32, 4)
    for (int t = 0; t < Tt; ++t)
        k_lstm_step<<<sgrid, 256>>>(x, x_index, t);

    k_fc1<<<dim3(Mm / 64, Bb / 64), 256>>>(fc1_w, fc1_b);
    k_fc2<<<Bb, 128>>>(fc2_w, fc2_b, out);
}